// round 7
// baseline (speedup 1.0000x reference)
#include <cuda_runtime.h>

#define NN 50000
#define TT 10
#define EE 1000000
#define HH 8

typedef unsigned long long u64;

// ---------------- device scratch (no allocations allowed) ----------------
__device__ float g_hidden[NN * HH];   // [N,H] hidden state
__device__ float g_s[NN];             // per-node sigmoid(message MLP)
__device__ float g_agg[NN];           // per-node aggregated messages
__device__ float g_eaT[TT * EE];      // edge_attr transposed to [T,E]

// ---------------- weights ----------------
// All sub-array offsets are 16B-aligned (verified) so ulonglong2 loads are legal.
struct __align__(16) Weights {
    float m1w1[9 * 32];    // @0
    float m1b1[32];        // @288
    float m1w2[32 * 32];   // @320
    float m1b2[32];        // @1344
    float m1w3[32];        // @1376
    float m1b3;            // @1408
    float pad[3];
    float m2w1[10 * 32];   // @1412
    float m2b1[32];        // @1732
    float m2w2[32 * 8];    // @1764
    float m2b2[8];         // @2020
    float ow1[8 * 16];     // @2028
    float ob1[16];         // @2156
    float ow2[16];         // @2172
    float ob2;             // @2188
};

struct WPtrs {
    const float *m1w1, *m1b1, *m1w2, *m1b2, *m1w3, *m1b3;
    const float *m2w1, *m2b1, *m2w2, *m2b2;
    const float *ow1, *ob1, *ow2, *ob2;
};

__device__ __forceinline__ void load_weights(Weights* W, const WPtrs p) {
    const int tid = threadIdx.x, nt = blockDim.x;
    for (int i = tid; i < 9 * 32; i += nt)  W->m1w1[i] = p.m1w1[i];
    for (int i = tid; i < 32; i += nt)      W->m1b1[i] = p.m1b1[i];
    for (int i = tid; i < 32 * 32; i += nt) W->m1w2[i] = p.m1w2[i];
    for (int i = tid; i < 32; i += nt)      W->m1b2[i] = p.m1b2[i];
    for (int i = tid; i < 32; i += nt)      W->m1w3[i] = p.m1w3[i];
    for (int i = tid; i < 10 * 32; i += nt) W->m2w1[i] = p.m2w1[i];
    for (int i = tid; i < 32; i += nt)      W->m2b1[i] = p.m2b1[i];
    for (int i = tid; i < 32 * 8; i += nt)  W->m2w2[i] = p.m2w2[i];
    for (int i = tid; i < 8; i += nt)       W->m2b2[i] = p.m2b2[i];
    for (int i = tid; i < 8 * 16; i += nt)  W->ow1[i] = p.ow1[i];
    for (int i = tid; i < 16; i += nt)      W->ob1[i] = p.ob1[i];
    for (int i = tid; i < 16; i += nt)      W->ow2[i] = p.ow2[i];
    if (tid == 0) { W->m1b3 = p.m1b3[0]; W->ob2 = p.ob2[0]; }
}

// ---------------- f32x2 packed primitives (Blackwell) ----------------
__device__ __forceinline__ u64 pk2(float lo, float hi) {
    u64 r; asm("mov.b64 %0, {%1,%2};" : "=l"(r) : "f"(lo), "f"(hi)); return r;
}
__device__ __forceinline__ void upk2(u64 v, float& lo, float& hi) {
    asm("mov.b64 {%0,%1}, %2;" : "=f"(lo), "=f"(hi) : "l"(v));
}
__device__ __forceinline__ u64 dup2(float x) { return pk2(x, x); }
__device__ __forceinline__ u64 ffma2(u64 a, u64 b, u64 c) {
    u64 d; asm("fma.rn.f32x2 %0, %1, %2, %3;" : "=l"(d) : "l"(a), "l"(b), "l"(c)); return d;
}
__device__ __forceinline__ u64 relu2(u64 v) {
    float lo, hi; upk2(v, lo, hi);
    return pk2(fmaxf(lo, 0.0f), fmaxf(hi, 0.0f));
}

__device__ __forceinline__ float fast_sigmoid(float z) {
    return 1.0f / (1.0f + __expf(-z));
}

// ===================== packed per-lane MLPs (1 node per lane) =====================
// Neuron pairs (2j, 2j+1) packed in one f32x2; weight pairs are contiguous in
// memory, inputs broadcast-duplicated. All weight loads are warp-uniform.

// Message MLP [x0, h(8)] -> 32 -> relu -> 32 -> relu -> 1 -> sigmoid
__device__ __forceinline__ float mlp1_pk(const Weights* W, u64 x0d, const u64 hd[HH]) {
    u64 a2[16];
    {
        const ulonglong2* bv = (const ulonglong2*)W->m1b1;
        const ulonglong2* wv = (const ulonglong2*)W->m1w1;   // row 0 (x0)
        #pragma unroll
        for (int j = 0; j < 8; j++) {
            ulonglong2 b = bv[j]; ulonglong2 w = wv[j];
            a2[2*j]   = ffma2(x0d, w.x, b.x);
            a2[2*j+1] = ffma2(x0d, w.y, b.y);
        }
    }
    #pragma unroll
    for (int i = 0; i < HH; i++) {
        u64 hi = hd[i];
        const ulonglong2* wr = (const ulonglong2*)(W->m1w1 + (i + 1) * 32);
        #pragma unroll
        for (int j = 0; j < 8; j++) {
            ulonglong2 w = wr[j];
            a2[2*j]   = ffma2(hi, w.x, a2[2*j]);
            a2[2*j+1] = ffma2(hi, w.y, a2[2*j+1]);
        }
    }
    // relu + unpack to scalars for broadcast-dup in layer 2
    float a[32];
    #pragma unroll
    for (int j = 0; j < 16; j++) {
        u64 r = relu2(a2[j]);
        upk2(r, a[2*j], a[2*j+1]);
    }

    u64 b2[16];
    {
        const ulonglong2* bv = (const ulonglong2*)W->m1b2;
        #pragma unroll
        for (int j = 0; j < 8; j++) { ulonglong2 b = bv[j]; b2[2*j] = b.x; b2[2*j+1] = b.y; }
    }
    #pragma unroll
    for (int i = 0; i < 32; i++) {
        u64 ai = dup2(a[i]);
        const ulonglong2* wr = (const ulonglong2*)(W->m1w2 + i * 32);
        #pragma unroll
        for (int j = 0; j < 8; j++) {
            ulonglong2 w = wr[j];
            b2[2*j]   = ffma2(ai, w.x, b2[2*j]);
            b2[2*j+1] = ffma2(ai, w.y, b2[2*j+1]);
        }
    }
    // layer 3: z = sum relu(b)*w3
    u64 z2 = 0ULL;
    {
        const ulonglong2* wv = (const ulonglong2*)W->m1w3;
        #pragma unroll
        for (int j = 0; j < 8; j++) {
            ulonglong2 w = wv[j];
            z2 = ffma2(relu2(b2[2*j]),   w.x, z2);
            z2 = ffma2(relu2(b2[2*j+1]), w.y, z2);
        }
    }
    float zl, zh; upk2(z2, zl, zh);
    return fast_sigmoid(zl + zh + W->m1b3);
}

// Update MLP [x1,h(8),agg](10) -> 32 -> relu -> 8 -> relu -> tanh
__device__ __forceinline__ void mlp2_pk(const Weights* W, const u64 in2[10], float hn[HH]) {
    u64 a2[16];
    {
        const ulonglong2* bv = (const ulonglong2*)W->m2b1;
        #pragma unroll
        for (int j = 0; j < 8; j++) { ulonglong2 b = bv[j]; a2[2*j] = b.x; a2[2*j+1] = b.y; }
    }
    #pragma unroll
    for (int i = 0; i < 10; i++) {
        u64 vi = in2[i];
        const ulonglong2* wr = (const ulonglong2*)(W->m2w1 + i * 32);
        #pragma unroll
        for (int j = 0; j < 8; j++) {
            ulonglong2 w = wr[j];
            a2[2*j]   = ffma2(vi, w.x, a2[2*j]);
            a2[2*j+1] = ffma2(vi, w.y, a2[2*j+1]);
        }
    }
    float a[32];
    #pragma unroll
    for (int j = 0; j < 16; j++) {
        u64 r = relu2(a2[j]);
        upk2(r, a[2*j], a[2*j+1]);
    }

    u64 b8[4];
    {
        const ulonglong2* bv = (const ulonglong2*)W->m2b2;
        ulonglong2 b0 = bv[0], b1 = bv[1];
        b8[0] = b0.x; b8[1] = b0.y; b8[2] = b1.x; b8[3] = b1.y;
    }
    #pragma unroll
    for (int i = 0; i < 32; i++) {
        u64 ai = dup2(a[i]);
        const ulonglong2* wr = (const ulonglong2*)(W->m2w2 + i * 8);
        ulonglong2 w0 = wr[0], w1 = wr[1];
        b8[0] = ffma2(ai, w0.x, b8[0]); b8[1] = ffma2(ai, w0.y, b8[1]);
        b8[2] = ffma2(ai, w1.x, b8[2]); b8[3] = ffma2(ai, w1.y, b8[3]);
    }
    // hidden_new = tanh(relu(z2))
    #pragma unroll
    for (int k = 0; k < 4; k++) {
        float lo, hi; upk2(relu2(b8[k]), lo, hi);
        hn[2*k]   = tanhf(lo);
        hn[2*k+1] = tanhf(hi);
    }
}

// Readout hidden(8) -> 16 -> relu -> 1 -> sigmoid (takes pre-dup'd hidden)
__device__ __forceinline__ float node_out_pk(const Weights* W, const u64 hd[HH]) {
    u64 o2[8];
    {
        const ulonglong2* bv = (const ulonglong2*)W->ob1;
        #pragma unroll
        for (int m = 0; m < 4; m++) { ulonglong2 b = bv[m]; o2[2*m] = b.x; o2[2*m+1] = b.y; }
    }
    #pragma unroll
    for (int i = 0; i < HH; i++) {
        u64 hi = hd[i];
        const ulonglong2* wr = (const ulonglong2*)(W->ow1 + i * 16);
        #pragma unroll
        for (int m = 0; m < 4; m++) {
            ulonglong2 w = wr[m];
            o2[2*m]   = ffma2(hi, w.x, o2[2*m]);
            o2[2*m+1] = ffma2(hi, w.y, o2[2*m+1]);
        }
    }
    u64 z2 = 0ULL;
    {
        const ulonglong2* wv = (const ulonglong2*)W->ow2;
        #pragma unroll
        for (int m = 0; m < 4; m++) {
            ulonglong2 w = wv[m];
            z2 = ffma2(relu2(o2[2*m]),   w.x, z2);
            z2 = ffma2(relu2(o2[2*m+1]), w.y, z2);
        }
    }
    float zl, zh; upk2(z2, zl, zh);
    return fast_sigmoid(zl + zh + W->ob2);
}

// ---------------- kernels ----------------

// Transpose edge_attr [E,T,1] -> [T,E] once.
__global__ void transpose_ea_kernel(const float* __restrict__ ea) {
    int e = blockIdx.x * blockDim.x + threadIdx.x;
    if (e >= EE) return;
    #pragma unroll
    for (int t = 0; t < TT; t++) g_eaT[t * EE + e] = ea[e * TT + t];
}

// Frame 0 prologue: hidden = 0, agg = 0, s = sigmoid(MLP1([x0, 0]))
__global__ void __launch_bounds__(128) prologue_kernel(const float* __restrict__ x, const WPtrs p) {
    __shared__ Weights W;
    load_weights(&W, p);
    __syncthreads();
    int n = blockIdx.x * blockDim.x + threadIdx.x;
    if (n >= NN) return;
    u64 hd[HH] = {0ULL,0ULL,0ULL,0ULL,0ULL,0ULL,0ULL,0ULL};
    u64 x0d = dup2(x[n * TT * 2 + 0]);
    g_s[n] = mlp1_pk(&W, x0d, hd);
    g_agg[n] = 0.0f;
    float4 z4 = make_float4(0.f, 0.f, 0.f, 0.f);
    ((float4*)g_hidden)[n * 2 + 0] = z4;
    ((float4*)g_hidden)[n * 2 + 1] = z4;
}

// Per-frame edge scatter: agg[dst] += s[src] * ea ; 4 edges per thread.
__global__ void edge_kernel(const int* __restrict__ ei, int t) {
    int e4 = blockIdx.x * blockDim.x + threadIdx.x;
    if (e4 >= EE / 4) return;
    int4 s4 = ((const int4*)(ei + t * EE))[e4];
    int4 d4 = ((const int4*)(ei + (TT + t) * EE))[e4];
    float4 a4 = ((const float4*)(g_eaT + t * EE))[e4];
    atomicAdd(&g_agg[d4.x], __ldg(&g_s[s4.x]) * a4.x);
    atomicAdd(&g_agg[d4.y], __ldg(&g_s[s4.y]) * a4.y);
    atomicAdd(&g_agg[d4.z], __ldg(&g_s[s4.z]) * a4.z);
    atomicAdd(&g_agg[d4.w], __ldg(&g_s[s4.w]) * a4.w);
}

// Per-frame node update (+ fused message-MLP for next frame), 1 node/lane, f32x2.
__global__ void __launch_bounds__(128) update_kernel(const float* __restrict__ x,
                                                     float* __restrict__ out,
                                                     const WPtrs p, int t) {
    __shared__ Weights W;
    load_weights(&W, p);
    __syncthreads();
    int n = blockIdx.x * blockDim.x + threadIdx.x;
    if (n >= NN) return;

    float4 h0 = ((const float4*)g_hidden)[n * 2 + 0];
    float4 h1 = ((const float4*)g_hidden)[n * 2 + 1];

    u64 in2[10];
    in2[0] = dup2(x[(n * TT + t) * 2 + 1]);
    in2[1] = dup2(h0.x); in2[2] = dup2(h0.y); in2[3] = dup2(h0.z); in2[4] = dup2(h0.w);
    in2[5] = dup2(h1.x); in2[6] = dup2(h1.y); in2[7] = dup2(h1.z); in2[8] = dup2(h1.w);
    in2[9] = dup2(g_agg[n]);   // AGG_MEAN=0, AGG_VAR=1 -> identity norm

    float hn[HH];
    mlp2_pk(&W, in2, hn);

    ((float4*)g_hidden)[n * 2 + 0] = make_float4(hn[0], hn[1], hn[2], hn[3]);
    ((float4*)g_hidden)[n * 2 + 1] = make_float4(hn[4], hn[5], hn[6], hn[7]);

    u64 hd[HH];
    #pragma unroll
    for (int i = 0; i < HH; i++) hd[i] = dup2(hn[i]);

    out[t * NN + n] = node_out_pk(&W, hd);

    if (t < TT - 1) {
        u64 x0d = dup2(x[(n * TT + t + 1) * 2 + 0]);
        g_s[n] = mlp1_pk(&W, x0d, hd);
        g_agg[n] = 0.0f;
    }
}

// ---------------- launch ----------------
extern "C" void kernel_launch(void* const* d_in, const int* in_sizes, int n_in,
                              void* d_out, int out_size) {
    const float* x  = (const float*)d_in[0];
    const int*   ei = (const int*)d_in[1];
    const float* ea = (const float*)d_in[2];
    WPtrs p;
    p.m1w1 = (const float*)d_in[3];  p.m1b1 = (const float*)d_in[4];
    p.m1w2 = (const float*)d_in[5];  p.m1b2 = (const float*)d_in[6];
    p.m1w3 = (const float*)d_in[7];  p.m1b3 = (const float*)d_in[8];
    p.m2w1 = (const float*)d_in[9];  p.m2b1 = (const float*)d_in[10];
    p.m2w2 = (const float*)d_in[11]; p.m2b2 = (const float*)d_in[12];
    p.ow1  = (const float*)d_in[13]; p.ob1  = (const float*)d_in[14];
    p.ow2  = (const float*)d_in[15]; p.ob2  = (const float*)d_in[16];
    float* out = (float*)d_out;

    transpose_ea_kernel<<<(EE + 255) / 256, 256>>>(ea);
    prologue_kernel<<<(NN + 127) / 128, 128>>>(x, p);
    for (int t = 0; t < TT; t++) {
        edge_kernel<<<(EE / 4 + 255) / 256, 256>>>(ei, t);
        update_kernel<<<(NN + 127) / 128, 128>>>(x, out, p, t);
    }
}